// round 2
// baseline (speedup 1.0000x reference)
#include <cuda_runtime.h>
#include <math.h>

// ---------------- problem constants ----------------
#define NLEV   16
#define TBL    524288u          // T = 2^19 entries per level
#define TMASK  (TBL - 1u)
#define HP1    2654435761u
#define HP2    805459861u

#define CAP    2097152          // expected N
#define KBITS  18
#define BINS   (1u << KBITS)    // 262144 morton buckets
#define TILE   1024             // scan tile
#define NTILES (BINS / TILE)    // 256

typedef unsigned long long ull;

// MLP weights in constant memory (warp-uniform -> LDCU, keeps LSU free)
__constant__ __align__(16) float cW1[32 * 64];
__constant__ __align__(16) float cW2[64 * 16];

// ---- static scratch (no dynamic allocation allowed) ----
__device__ unsigned g_keys[CAP];
__device__ unsigned g_perm[CAP];
__device__ float    g_sx[CAP];
__device__ float    g_sy[CAP];
__device__ float    g_sz[CAP];
__device__ unsigned g_hist[BINS];
__device__ unsigned g_offs[BINS];
__device__ unsigned g_part[NTILES];

struct LevelParams {
    float    resf[NLEV];   // (float)res[l]
    unsigned s[NLEV];      // res[l] + 1  (dense stride)
    unsigned dense[NLEV];  // (res+1)^3 <= T ?
};

// ---------------- packed f32x2 helpers ----------------
__device__ __forceinline__ ull pack2(float v) {
    ull r; unsigned u = __float_as_uint(v);
    asm("mov.b64 %0, {%1,%1};" : "=l"(r) : "r"(u));
    return r;
}
__device__ __forceinline__ ull fma2(ull a, ull b, ull c) {
    ull d;
    asm("fma.rn.f32x2 %0, %1, %2, %3;" : "=l"(d) : "l"(a), "l"(b), "l"(c));
    return d;
}
__device__ __forceinline__ float2 unpack2(ull v) {
    unsigned lo, hi;
    asm("mov.b64 {%0,%1}, %2;" : "=r"(lo), "=r"(hi) : "l"(v));
    return make_float2(__uint_as_float(lo), __uint_as_float(hi));
}

// Predicated 8B gather: no BSSY/BSYNC, inactive lanes contribute no wavefront.
__device__ __forceinline__ void ldg64_pred(const float2* p, unsigned en,
                                           float& vx, float& vy) {
    asm volatile("{\n\t.reg .pred p;\n\tsetp.ne.u32 p, %3, 0;\n\t"
                 "@p ld.global.nc.v2.f32 {%0,%1}, [%2];\n\t}"
                 : "+f"(vx), "+f"(vy) : "l"(p), "r"(en));
}

// ---------------- morton ----------------
__device__ __forceinline__ unsigned part1by2(unsigned x) {
    x &= 0x3ffu;
    x = (x | (x << 16)) & 0x030000FFu;
    x = (x | (x << 8))  & 0x0300F00Fu;
    x = (x | (x << 4))  & 0x030C30C3u;
    x = (x | (x << 2))  & 0x09249249u;
    return x;
}
__device__ __forceinline__ float clip01(float v) {
    return fminf(fmaxf((v + 1.0f) * 0.5f, 0.0f), 1.0f);
}
__device__ __forceinline__ unsigned morton_key(float x, float y, float z) {
    unsigned ix = min((unsigned)(clip01(x) * 64.0f), 63u);
    unsigned iy = min((unsigned)(clip01(y) * 64.0f), 63u);
    unsigned iz = min((unsigned)(clip01(z) * 64.0f), 63u);
    return part1by2(ix) | (part1by2(iy) << 1) | (part1by2(iz) << 2);
}

// ---------------- sort pipeline kernels ----------------
__global__ void k_zero_hist() {
    unsigned g = blockIdx.x * blockDim.x + threadIdx.x;
    if (g < BINS) g_hist[g] = 0u;
}

__global__ void k_keys_hist(const float* __restrict__ xyzs, int N) {
    int i = blockIdx.x * blockDim.x + threadIdx.x;
    if (i >= N) return;
    unsigned k = morton_key(xyzs[3 * i], xyzs[3 * i + 1], xyzs[3 * i + 2]);
    g_keys[i] = k;
    atomicAdd(&g_hist[k], 1u);
}

__global__ void k_scan_tiles() {
    __shared__ unsigned sm[TILE];
    unsigned t = threadIdx.x;
    unsigned g = blockIdx.x * TILE + t;
    unsigned v = g_hist[g];
    sm[t] = v;
    __syncthreads();
#pragma unroll
    for (unsigned d = 1; d < TILE; d <<= 1) {
        unsigned add = (t >= d) ? sm[t - d] : 0u;
        __syncthreads();
        sm[t] += add;
        __syncthreads();
    }
    g_offs[g] = sm[t] - v;           // exclusive within tile
    if (t == TILE - 1) g_part[blockIdx.x] = sm[t];
}

__global__ void k_scan_part() {
    __shared__ unsigned sm[NTILES];
    unsigned t = threadIdx.x;
    unsigned v = g_part[t];
    sm[t] = v;
    __syncthreads();
#pragma unroll
    for (unsigned d = 1; d < NTILES; d <<= 1) {
        unsigned add = (t >= d) ? sm[t - d] : 0u;
        __syncthreads();
        sm[t] += add;
        __syncthreads();
    }
    g_part[t] = sm[t] - v;           // exclusive tile offsets
}

__global__ void k_addback() {
    unsigned g = blockIdx.x * blockDim.x + threadIdx.x;
    if (g < BINS) g_offs[g] += g_part[g >> 10];
}

__global__ void k_scatter(const float* __restrict__ xyzs, int N) {
    int i = blockIdx.x * blockDim.x + threadIdx.x;
    if (i >= N) return;
    unsigned k   = g_keys[i];
    unsigned pos = atomicAdd(&g_offs[k], 1u);
    g_perm[pos] = (unsigned)i;
    g_sx[pos] = xyzs[3 * i];
    g_sy[pos] = xyzs[3 * i + 1];
    g_sz[pos] = xyzs[3 * i + 2];
}

// ---------------- fused kernel: hashgrid encode + MLP ----------------
__global__ void __launch_bounds__(256)
hashgrid_mlp_kernel(const float* __restrict__ xyzs,
                    const float* __restrict__ tables,
                    float* __restrict__ out,
                    int N, int use_perm, LevelParams lp)
{
    int i = blockIdx.x * blockDim.x + threadIdx.x;
    if (i >= N) return;

    int pid;
    float x, y, z;
    if (use_perm) {
        pid = (int)g_perm[i];
        x = g_sx[i]; y = g_sy[i]; z = g_sz[i];
    } else {
        pid = i;
        x = xyzs[3 * i]; y = xyzs[3 * i + 1]; z = xyzs[3 * i + 2];
    }

    float x01 = clip01(x), y01 = clip01(y), z01 = clip01(z);

    // Layer-1 accumulators (64 floats as 32 packed pairs), fused into level loop
    ull hp[32];
#pragma unroll
    for (int j = 0; j < 32; j++) hp[j] = 0ull;

#pragma unroll 1
    for (int l = 0; l < NLEV; l++) {
        const float2* __restrict__ tab =
            reinterpret_cast<const float2*>(tables) + (size_t)l * TBL;

        float rf = lp.resf[l];
        float px = x01 * rf, py = y01 * rf, pz = z01 * rf;
        float fpx = floorf(px), fpy = floorf(py), fpz = floorf(pz);
        float fx = px - fpx, fy = py - fpy, fz = pz - fpz;
        unsigned ix = (unsigned)fpx, iy = (unsigned)fpy, iz = (unsigned)fpz;
        float wx0 = 1.0f - fx, wy0 = 1.0f - fy, wz0 = 1.0f - fz;

        unsigned i0a[4], i1a[4];
        float    wyz[4];
        if (lp.dense[l]) {
            unsigned s = lp.s[l];
#pragma unroll
            for (int k = 0; k < 2; k++) {
#pragma unroll
                for (int j = 0; j < 2; j++) {
                    unsigned a = s * ((iy + (unsigned)j) + s * (iz + (unsigned)k));
                    int c = k * 2 + j;
                    i0a[c] = ix + a;
                    i1a[c] = ix + 1u + a;
                    wyz[c] = (j ? fy : wy0) * (k ? fz : wz0);
                }
            }
        } else {
            unsigned hy0 = iy * HP1;
            unsigned hz0 = iz * HP2;
#pragma unroll
            for (int k = 0; k < 2; k++) {
#pragma unroll
                for (int j = 0; j < 2; j++) {
                    unsigned a = (hy0 + (j ? HP1 : 0u)) ^ (hz0 + (k ? HP2 : 0u));
                    int c = k * 2 + j;
                    i0a[c] = (ix ^ a) & TMASK;
                    i1a[c] = ((ix + 1u) ^ a) & TMASK;
                    wyz[c] = (j ? fy : wy0) * (k ? fz : wz0);
                }
            }
        }

        // Branchless paired gather: one aligned LDG.128 always covers the
        // i0 entry (and i1 too when (i0^i1)==1); predicated LDG.64 otherwise.
        float e0 = 0.0f, e1 = 0.0f;
#pragma unroll
        for (int c = 0; c < 4; c++) {
            unsigned a0 = i0a[c], a1 = i1a[c];
            float w0 = wx0 * wyz[c];
            float w1 = fx  * wyz[c];
            const float4* bp =
                reinterpret_cast<const float4*>(tab + (a0 & ~1u));
            float4 q = __ldg(bp);
            bool odd = (a0 & 1u) != 0u;
            float v0x = odd ? q.z : q.x;
            float v0y = odd ? q.w : q.y;
            float v1x = odd ? q.x : q.z;   // valid iff pair-adjacent
            float v1y = odd ? q.y : q.w;
            unsigned nadj = ((a0 ^ a1) != 1u) ? 1u : 0u;
            ldg64_pred(tab + a1, nadj, v1x, v1y);
            e0 = fmaf(w0, v0x, fmaf(w1, v1x, e0));
            e1 = fmaf(w0, v0y, fmaf(w1, v1y, e1));
        }

        // Fused MLP layer-1 accumulation for this level's two features
        ull p0 = pack2(e0), p1 = pack2(e1);
        const ulonglong2* r0 =
            reinterpret_cast<const ulonglong2*>(cW1 + (2 * l) * 64);
        const ulonglong2* r1 = r0 + 16;
#pragma unroll
        for (int j = 0; j < 16; j++) {
            ulonglong2 wa = r0[j];
            ulonglong2 wb = r1[j];
            hp[2 * j]     = fma2(p0, wa.x, hp[2 * j]);
            hp[2 * j + 1] = fma2(p0, wa.y, hp[2 * j + 1]);
            hp[2 * j]     = fma2(p1, wb.x, hp[2 * j]);
            hp[2 * j + 1] = fma2(p1, wb.y, hp[2 * j + 1]);
        }
    }

    // relu
    float h[64];
#pragma unroll
    for (int j = 0; j < 32; j++) {
        float2 p = unpack2(hp[j]);
        h[2 * j]     = fmaxf(p.x, 0.0f);
        h[2 * j + 1] = fmaxf(p.y, 0.0f);
    }

    // layer 2: out = h @ W2, W2[64][16]
    ull op[8];
#pragma unroll
    for (int j = 0; j < 8; j++) op[j] = 0ull;
#pragma unroll
    for (int i2 = 0; i2 < 64; i2++) {
        ull ee = pack2(h[i2]);
        const ulonglong2* wrow =
            reinterpret_cast<const ulonglong2*>(cW2 + i2 * 16);
#pragma unroll
        for (int j = 0; j < 4; j++) {
            ulonglong2 w = wrow[j];
            op[2 * j]     = fma2(ee, w.x, op[2 * j]);
            op[2 * j + 1] = fma2(ee, w.y, op[2 * j + 1]);
        }
    }

    float o[16];
#pragma unroll
    for (int j = 0; j < 8; j++) {
        float2 p = unpack2(op[j]);
        o[2 * j]     = p.x;
        o[2 * j + 1] = p.y;
    }

    out[pid] = expf(o[0]);
    float* g = out + (size_t)N + (size_t)pid * 15;
#pragma unroll
    for (int k = 0; k < 15; k++) g[k] = o[k + 1];
}

// ---------------- host ----------------
static LevelParams make_level_params()
{
    LevelParams lp;
    double pls = exp(log(2048.0 / 16.0) / (double)(NLEV - 1));
    for (int l = 0; l < NLEV; l++) {
        int r = (int)ceil(16.0 * pow(pls, (double)l));
        lp.resf[l]  = (float)r;
        lp.s[l]     = (unsigned)(r + 1);
        long long s = (long long)(r + 1);
        lp.dense[l] = (s * s * s <= (long long)TBL) ? 1u : 0u;
    }
    return lp;
}

extern "C" void kernel_launch(void* const* d_in, const int* in_sizes, int n_in,
                              void* d_out, int out_size)
{
    (void)n_in; (void)out_size;
    const float* xyzs   = (const float*)d_in[0];
    const float* tables = (const float*)d_in[1];
    int N = in_sizes[0] / 3;

    cudaMemcpyToSymbolAsync(cW1, d_in[2], 32 * 64 * sizeof(float), 0,
                            cudaMemcpyDeviceToDevice, 0);
    cudaMemcpyToSymbolAsync(cW2, d_in[3], 64 * 16 * sizeof(float), 0,
                            cudaMemcpyDeviceToDevice, 0);

    LevelParams lp = make_level_params();

    int use_perm = (N <= CAP) ? 1 : 0;
    int blk = 256;
    int gridN = (N + blk - 1) / blk;

    if (use_perm) {
        k_zero_hist<<<BINS / 256, 256>>>();
        k_keys_hist<<<gridN, blk>>>(xyzs, N);
        k_scan_tiles<<<NTILES, TILE>>>();
        k_scan_part<<<1, NTILES>>>();
        k_addback<<<BINS / 256, 256>>>();
        k_scatter<<<gridN, blk>>>(xyzs, N);
    }

    hashgrid_mlp_kernel<<<gridN, blk>>>(xyzs, tables, (float*)d_out,
                                        N, use_perm, lp);
}